// round 15
// baseline (speedup 1.0000x reference)
#include <cuda_runtime.h>
#include <cuda_bf16.h>
#include <math.h>

#define MAXN 100352
#define MAXE 1600000
#define SCAN_CHUNK 1024

__device__ int   g_is64;
__device__ int   g_cnt[MAXN];
__device__ int   g_cursor[MAXN];
__device__ int   g_off[MAXN + 1];
__device__ int   g_bsum[128];
__device__ int   g_srcsort[MAXE];
__device__ float g_msgvar[(size_t)MAXN * 128]; // [N][0:64)=msg, [64:128)=var

// ---------------------------------------------------------------------------
// Pass 0: zero counters; block 0 also detects edge_index dtype
// (int64 little-endian with values < 2^31 => odd int32 words all zero).
// ---------------------------------------------------------------------------
__global__ void ra_init_kernel(const int* __restrict__ ei32, int N) {
    int i = blockIdx.x * blockDim.x + threadIdx.x;
    if (i < N) g_cnt[i] = 0;
    if (blockIdx.x == 0) {
        __shared__ int nz;
        if (threadIdx.x == 0) nz = 0;
        __syncthreads();
        int v = ei32[2 * threadIdx.x + 1];
        if (v != 0) nz = 1;                  // benign race
        __syncthreads();
        if (threadIdx.x == 0) g_is64 = nz ? 0 : 1;
    }
}

__device__ __forceinline__ int load_src(const int* ei32, int E, int e) {
    return g_is64 ? ei32[2 * e] : ei32[e];
}
__device__ __forceinline__ int load_dst(const int* ei32, int E, int e) {
    return g_is64 ? ei32[2 * (E + e)] : ei32[E + e];
}

// ---------------------------------------------------------------------------
__global__ void ra_hist_kernel(const int* __restrict__ ei32, int E, int N) {
    int e = blockIdx.x * blockDim.x + threadIdx.x;
    if (e < E) {
        int d = load_dst(ei32, E, e);
        if ((unsigned)d < (unsigned)N) atomicAdd(&g_cnt[d], 1);
    }
}

// ---------------------------------------------------------------------------
__global__ void __launch_bounds__(256) ra_scan1_kernel(int N) {
    __shared__ int wsum[8];
    int base = blockIdx.x * SCAN_CHUNK + threadIdx.x * 4;
    int s = 0;
#pragma unroll
    for (int j = 0; j < 4; ++j) {
        int i = base + j;
        if (i < N) s += g_cnt[i];
    }
#pragma unroll
    for (int o = 16; o > 0; o >>= 1) s += __shfl_xor_sync(0xffffffffu, s, o);
    if ((threadIdx.x & 31) == 0) wsum[threadIdx.x >> 5] = s;
    __syncthreads();
    if (threadIdx.x == 0) {
        int t = 0;
#pragma unroll
        for (int w = 0; w < 8; ++w) t += wsum[w];
        g_bsum[blockIdx.x] = t;
    }
}

__global__ void __launch_bounds__(256) ra_scan3_kernel(int nb, int N) {
    __shared__ int sb[128];
    __shared__ int wtot[4];
    __shared__ int wpre[8];
    int tid = threadIdx.x;
    int lane = tid & 31, w = tid >> 5;

    {
        int v = (tid < nb) ? g_bsum[tid] : 0;
        int incl = v;
#pragma unroll
        for (int o = 1; o < 32; o <<= 1) {
            int u = __shfl_up_sync(0xffffffffu, incl, o);
            if (lane >= o) incl += u;
        }
        if (lane == 31 && w < 4) wtot[w] = incl;
        __syncthreads();
        if (tid < 128) {
            int wbase = 0;
#pragma unroll
            for (int i = 0; i < 4; ++i) if (i < w) wbase += wtot[i];
            sb[tid] = wbase + incl - v;
        }
        __syncthreads();
        if (blockIdx.x == 0 && tid == 0) g_off[N] = sb[nb - 1] + g_bsum[nb - 1];
    }

    int bbase = sb[blockIdx.x];
    int base = blockIdx.x * SCAN_CHUNK + tid * 4;
    int c[4];
    int s = 0;
#pragma unroll
    for (int j = 0; j < 4; ++j) {
        int i = base + j;
        c[j] = (i < N) ? g_cnt[i] : 0;
        s += c[j];
    }
    int incl = s;
#pragma unroll
    for (int o = 1; o < 32; o <<= 1) {
        int u = __shfl_up_sync(0xffffffffu, incl, o);
        if (lane >= o) incl += u;
    }
    if (lane == 31) wpre[w] = incl;
    __syncthreads();
    int run = bbase + incl - s;
#pragma unroll
    for (int i = 0; i < 8; ++i) if (i < w) run += wpre[i];
#pragma unroll
    for (int j = 0; j < 4; ++j) {
        int i = base + j;
        if (i < N) { g_off[i] = run; g_cursor[i] = run; }
        run += c[j];
    }
}

// ---------------------------------------------------------------------------
__global__ void ra_scatter_kernel(const int* __restrict__ ei32, int E, int N) {
    int e = blockIdx.x * blockDim.x + threadIdx.x;
    if (e < E) {
        int s = load_src(ei32, E, e);
        int d = load_dst(ei32, E, e);
        if ((unsigned)d < (unsigned)N && (unsigned)s < (unsigned)N) {
            int p = atomicAdd(&g_cursor[d], 1);
            g_srcsort[p] = s;
        }
    }
}

// ---------------------------------------------------------------------------
// Packed f32x2 helpers
// ---------------------------------------------------------------------------
#define MUL2D(d, a, b)    asm("mul.rn.f32x2 %0, %1, %2;" : "=l"(d) : "l"(a), "l"(b))
#define FMA2A(acc, a, b)  asm("fma.rn.f32x2 %0, %1, %2, %0;" : "+l"(acc) : "l"(a), "l"(b))
#define ADD2A(acc, a)     asm("add.rn.f32x2 %0, %1, %0;" : "+l"(acc) : "l"(a))
#define PACKDUP(d, a)     asm("mov.b64 %0, {%1, %1};" : "=l"(d) : "f"(a))
#define PACK2(d, a)       PACKDUP(d, a)
#define UNPK(lo, hi, v)   asm("mov.b64 {%0, %1}, %2;" : "=f"(lo), "=f"(hi) : "l"(v))
#define UNPACK2(lo, hi, v) UNPK(lo, hi, v)
#define FMA2(acc, a, b)   FMA2A(acc, a, b)

// ---------------------------------------------------------------------------
// Pass 4: one warp per dst node, 4 edges in flight. Quarter-warp q4 owns edge
// b+4t+q4; lane owns 8 dims (two LDG.128 = four f32x2 pairs). Main loop has
// NO validity logic (prefetch clamped to e-1); tail of cnt&3 edges handled
// once with a q4<rem mask. Direct exp (shift-invariant softmax).
// ---------------------------------------------------------------------------
__global__ void __launch_bounds__(256)
ra_agg_kernel(const float* __restrict__ x, int N) {
    int gtid = blockIdx.x * blockDim.x + threadIdx.x;
    int n = gtid >> 5;
    if (n >= N) return;
    int lane = threadIdx.x & 31;
    int q4 = lane >> 3;       // quarter id 0..3
    int ql = lane & 7;        // owns dims 8*ql .. 8*ql+7

    int b = g_off[n];
    int e = g_off[n + 1];
    int cnt = e - b;

    float* row = g_msgvar + (size_t)n * 128;
    if (cnt == 0) {
        if (q4 == 0) {
            *reinterpret_cast<float4*>(row + 8 * ql)      = make_float4(0.f, 0.f, 0.f, 0.f);
            *reinterpret_cast<float4*>(row + 8 * ql + 4)  = make_float4(0.f, 0.f, 0.f, 0.f);
            *reinterpret_cast<float4*>(row + 64 + 8 * ql) = make_float4(0.f, 0.f, 0.f, 0.f);
            *reinterpret_cast<float4*>(row + 68 + 8 * ql) = make_float4(0.f, 0.f, 0.f, 0.f);
        }
        return;
    }

    const float* xdrow = x + (size_t)n * 64 + 8 * ql;
    ulonglong2 xd0 = *reinterpret_cast<const ulonglong2*>(xdrow);
    ulonglong2 xd1 = *reinterpret_cast<const ulonglong2*>(xdrow + 4);

    unsigned long long mg[4] = {0, 0, 0, 0};
    unsigned long long sa[4] = {0, 0, 0, 0};
    unsigned long long qa[4] = {0, 0, 0, 0};
    float denom = 0.f;

    int full = cnt >> 2;
    int rem  = cnt & 3;

    ulonglong2 xs0, xs1;
    {
        int i0 = min(b + q4, e - 1);
        int sidx = g_srcsort[i0];
        const float* sr = x + (size_t)sidx * 64 + 8 * ql;
        xs0 = *reinterpret_cast<const ulonglong2*>(sr);
        xs1 = *reinterpret_cast<const ulonglong2*>(sr + 4);
    }

    for (int t = 0; t < full; ++t) {
        int i_nxt = min(b + 4 * (t + 1) + q4, e - 1);
        int snxt = g_srcsort[i_nxt];
        const float* nr = x + (size_t)snxt * 64 + 8 * ql;
        ulonglong2 xn0 = *reinterpret_cast<const ulonglong2*>(nr);
        ulonglong2 xn1 = *reinterpret_cast<const ulonglong2*>(nr + 4);

        unsigned long long tdp;
        MUL2D(tdp, xs0.x, xd0.x);
        FMA2A(tdp, xs0.y, xd0.y);
        FMA2A(tdp, xs1.x, xd1.x);
        FMA2A(tdp, xs1.y, xd1.y);
        float plo, phi; UNPK(plo, phi, tdp);
        float p = plo + phi;
        p += __shfl_xor_sync(0xffffffffu, p, 4);
        p += __shfl_xor_sync(0xffffffffu, p, 2);
        p += __shfl_xor_sync(0xffffffffu, p, 1);

        float w = __expf(p * 0.125f);
        denom += w;
        unsigned long long w2; PACKDUP(w2, w);
        FMA2A(mg[0], w2, xs0.x); FMA2A(mg[1], w2, xs0.y);
        FMA2A(mg[2], w2, xs1.x); FMA2A(mg[3], w2, xs1.y);
        ADD2A(sa[0], xs0.x); ADD2A(sa[1], xs0.y);
        ADD2A(sa[2], xs1.x); ADD2A(sa[3], xs1.y);
        FMA2A(qa[0], xs0.x, xs0.x); FMA2A(qa[1], xs0.y, xs0.y);
        FMA2A(qa[2], xs1.x, xs1.x); FMA2A(qa[3], xs1.y, xs1.y);

        xs0 = xn0; xs1 = xn1;
    }

    if (rem) {
        // xs holds x[srcsort[min(b+4*full+q4, e-1)]] — valid tail edge iff q4 < rem
        unsigned long long tdp;
        MUL2D(tdp, xs0.x, xd0.x);
        FMA2A(tdp, xs0.y, xd0.y);
        FMA2A(tdp, xs1.x, xd1.x);
        FMA2A(tdp, xs1.y, xd1.y);
        float plo, phi; UNPK(plo, phi, tdp);
        float p = plo + phi;
        p += __shfl_xor_sync(0xffffffffu, p, 4);
        p += __shfl_xor_sync(0xffffffffu, p, 2);
        p += __shfl_xor_sync(0xffffffffu, p, 1);
        float w = __expf(p * 0.125f);
        if (q4 < rem) {
            denom += w;
            unsigned long long w2; PACKDUP(w2, w);
            FMA2A(mg[0], w2, xs0.x); FMA2A(mg[1], w2, xs0.y);
            FMA2A(mg[2], w2, xs1.x); FMA2A(mg[3], w2, xs1.y);
            ADD2A(sa[0], xs0.x); ADD2A(sa[1], xs0.y);
            ADD2A(sa[2], xs1.x); ADD2A(sa[3], xs1.y);
            FMA2A(qa[0], xs0.x, xs0.x); FMA2A(qa[1], xs0.y, xs0.y);
            FMA2A(qa[2], xs1.x, xs1.x); FMA2A(qa[3], xs1.y, xs1.y);
        }
    }

    // unpack to 24 scalars + denom, merge quarter-warps: xor 8 then xor 16
    float mgf[8], sf[8], qf[8];
#pragma unroll
    for (int j = 0; j < 4; ++j) {
        UNPK(mgf[2 * j], mgf[2 * j + 1], mg[j]);
        UNPK(sf[2 * j],  sf[2 * j + 1],  sa[j]);
        UNPK(qf[2 * j],  qf[2 * j + 1],  qa[j]);
    }
    denom += __shfl_xor_sync(0xffffffffu, denom, 8);
    denom += __shfl_xor_sync(0xffffffffu, denom, 16);
#pragma unroll
    for (int j = 0; j < 8; ++j) {
        mgf[j] += __shfl_xor_sync(0xffffffffu, mgf[j], 8);
        mgf[j] += __shfl_xor_sync(0xffffffffu, mgf[j], 16);
        sf[j]  += __shfl_xor_sync(0xffffffffu, sf[j], 8);
        sf[j]  += __shfl_xor_sync(0xffffffffu, sf[j], 16);
        qf[j]  += __shfl_xor_sync(0xffffffffu, qf[j], 8);
        qf[j]  += __shfl_xor_sync(0xffffffffu, qf[j], 16);
    }

    if (q4 == 0) {
        float invD = 1.0f / denom;
        float invc = 1.0f / (float)cnt;
        float o[16];
#pragma unroll
        for (int j = 0; j < 8; ++j) o[j] = mgf[j] * invD;
#pragma unroll
        for (int j = 0; j < 8; ++j) {
            float m = sf[j] * invc;
            o[8 + j] = fmaxf(fmaf(-m, m, qf[j] * invc), 0.f);
        }
        *reinterpret_cast<float4*>(row + 8 * ql)      = make_float4(o[0], o[1], o[2], o[3]);
        *reinterpret_cast<float4*>(row + 8 * ql + 4)  = make_float4(o[4], o[5], o[6], o[7]);
        *reinterpret_cast<float4*>(row + 64 + 8 * ql) = make_float4(o[8], o[9], o[10], o[11]);
        *reinterpret_cast<float4*>(row + 68 + 8 * ql) = make_float4(o[12], o[13], o[14], o[15]);
    }
}

// ---------------------------------------------------------------------------
// Pass 5: fused GEMM  out = x@Ws^T + msg@Wn^T + var@Wv^T + (bs+bn+bv)
// (R10 configuration: pitch-64 A tile, f32x2 packed FMA.)
// ---------------------------------------------------------------------------
__global__ void __launch_bounds__(256)
ra_gemm_kernel(const float* __restrict__ x,
               const float* __restrict__ Ws, const float* __restrict__ bs,
               const float* __restrict__ Wn, const float* __restrict__ bn,
               const float* __restrict__ Wv, const float* __restrict__ bv,
               float* __restrict__ out, int N) {
    __shared__ __align__(16) float Ash[128 * 64];
    __shared__ __align__(16) float Bsh[64 * 64];

    int tid = threadIdx.x;
    int tx = tid & 7;
    int ty = tid >> 3;
    int n0 = blockIdx.x * 128;

    unsigned long long acc[4][4];
#pragma unroll
    for (int r = 0; r < 4; ++r)
#pragma unroll
        for (int p = 0; p < 4; ++p) acc[r][p] = 0ull;

    for (int kc = 0; kc < 3; ++kc) {
        {
            const float* ap; int pitch, cb;
            if (kc == 0) { ap = x;        pitch = 64;  cb = 0; }
            else         { ap = g_msgvar; pitch = 128; cb = (kc - 1) * 64; }
            for (int i = tid; i < 128 * 64; i += 256) {
                int node = i >> 6, k = i & 63;
                int nn = n0 + node;
                Ash[i] = (nn < N) ? ap[(size_t)nn * pitch + cb + k] : 0.0f;
            }
        }
        {
            const float* wp = (kc == 0) ? Ws : ((kc == 1) ? Wn : Wv);
            for (int i = tid; i < 64 * 64; i += 256) {
                int ii = i >> 6;
                int kk = i & 63;
                int c4 = (ii >> 2) ^ (kk & 15);
                Bsh[kk * 64 + (c4 << 2) + (ii & 3)] = wp[i];
            }
        }
        __syncthreads();

        const float* arow = &Ash[(ty * 4) * 64];
        for (int k0 = 0; k0 < 64; k0 += 16) {
#pragma unroll
            for (int u = 0; u < 16; ++u) {
                int k = k0 + u;
                float a0 = arow[0 * 64 + k];
                float a1 = arow[1 * 64 + k];
                float a2 = arow[2 * 64 + k];
                float a3 = arow[3 * 64 + k];
                unsigned long long A0, A1, A2, A3;
                PACK2(A0, a0); PACK2(A1, a1); PACK2(A2, a2); PACK2(A3, a3);

                int sw0 = (((tx * 2)     ^ u) << 2);
                int sw1 = (((tx * 2 + 1) ^ u) << 2);
                ulonglong2 B0 = *reinterpret_cast<const ulonglong2*>(&Bsh[k * 64 + sw0]);
                ulonglong2 B1 = *reinterpret_cast<const ulonglong2*>(&Bsh[k * 64 + sw1]);

                FMA2(acc[0][0], A0, B0.x); FMA2(acc[0][1], A0, B0.y);
                FMA2(acc[0][2], A0, B1.x); FMA2(acc[0][3], A0, B1.y);
                FMA2(acc[1][0], A1, B0.x); FMA2(acc[1][1], A1, B0.y);
                FMA2(acc[1][2], A1, B1.x); FMA2(acc[1][3], A1, B1.y);
                FMA2(acc[2][0], A2, B0.x); FMA2(acc[2][1], A2, B0.y);
                FMA2(acc[2][2], A2, B1.x); FMA2(acc[2][3], A2, B1.y);
                FMA2(acc[3][0], A3, B0.x); FMA2(acc[3][1], A3, B0.y);
                FMA2(acc[3][2], A3, B1.x); FMA2(acc[3][3], A3, B1.y);
            }
        }
        __syncthreads();
    }

    float bsum[8];
#pragma unroll
    for (int p = 0; p < 8; ++p) {
        int d = tx * 8 + p;
        bsum[p] = bs[d] + bn[d] + bv[d];
    }
#pragma unroll
    for (int r = 0; r < 4; ++r) {
        int n = n0 + ty * 4 + r;
        if (n < N) {
            float o[8];
#pragma unroll
            for (int p = 0; p < 4; ++p) {
                float lo, hi;
                UNPACK2(lo, hi, acc[r][p]);
                o[2 * p]     = lo + bsum[2 * p];
                o[2 * p + 1] = hi + bsum[2 * p + 1];
            }
            float4* dst = reinterpret_cast<float4*>(out + (size_t)n * 64 + tx * 8);
            dst[0] = make_float4(o[0], o[1], o[2], o[3]);
            dst[1] = make_float4(o[4], o[5], o[6], o[7]);
        }
    }
}

// ---------------------------------------------------------------------------
extern "C" void kernel_launch(void* const* d_in, const int* in_sizes, int n_in,
                              void* d_out, int out_size) {
    const float* x  = (const float*)d_in[0];
    const int*   ei = (const int*)d_in[1];
    const float* Ws = (const float*)d_in[2];
    const float* bs = (const float*)d_in[3];
    const float* Wn = (const float*)d_in[4];
    const float* bn = (const float*)d_in[5];
    const float* Wv = (const float*)d_in[6];
    const float* bv = (const float*)d_in[7];
    float* out = (float*)d_out;

    int N = in_sizes[0] / 64;
    int E = in_sizes[1] / 2;
    int nb = (N + SCAN_CHUNK - 1) / SCAN_CHUNK;

    ra_init_kernel<<<(N + 255) / 256, 256>>>(ei, N);
    ra_hist_kernel<<<(E + 255) / 256, 256>>>(ei, E, N);
    ra_scan1_kernel<<<nb, 256>>>(N);
    ra_scan3_kernel<<<nb, 256>>>(nb, N);
    ra_scatter_kernel<<<(E + 255) / 256, 256>>>(ei, E, N);
    ra_agg_kernel<<<(N * 32 + 255) / 256, 256>>>(x, N);
    ra_gemm_kernel<<<(N + 127) / 128, 256>>>(x, Ws, bs, Wn, bn, Wv, bv, out, N);
}

// round 16
// speedup vs baseline: 1.0448x; 1.0448x over previous
#include <cuda_runtime.h>
#include <cuda_bf16.h>
#include <math.h>

#define MAXN 100352
#define MAXE 1600000
#define SCAN_CHUNK 1024

__device__ int   g_is64;
__device__ int   g_cnt[MAXN];
__device__ int   g_cursor[MAXN];
__device__ int   g_off[MAXN + 1];
__device__ int   g_bsum[128];
__device__ int   g_srcsort[MAXE];
__device__ float g_msgvar[(size_t)MAXN * 128]; // [N][0:64)=msg, [64:128)=var

// ---------------------------------------------------------------------------
// Pass 0: zero counters; block 0 also detects edge_index dtype
// (int64 little-endian with values < 2^31 => odd int32 words all zero).
// ---------------------------------------------------------------------------
__global__ void ra_init_kernel(const int* __restrict__ ei32, int N) {
    int i = blockIdx.x * blockDim.x + threadIdx.x;
    if (i < N) g_cnt[i] = 0;
    if (blockIdx.x == 0) {
        __shared__ int nz;
        if (threadIdx.x == 0) nz = 0;
        __syncthreads();
        int v = ei32[2 * threadIdx.x + 1];
        if (v != 0) nz = 1;                  // benign race
        __syncthreads();
        if (threadIdx.x == 0) g_is64 = nz ? 0 : 1;
    }
}

__device__ __forceinline__ int load_src(const int* ei32, int E, int e) {
    return g_is64 ? ei32[2 * e] : ei32[e];
}
__device__ __forceinline__ int load_dst(const int* ei32, int E, int e) {
    return g_is64 ? ei32[2 * (E + e)] : ei32[E + e];
}

// ---------------------------------------------------------------------------
__global__ void ra_hist_kernel(const int* __restrict__ ei32, int E, int N) {
    int e = blockIdx.x * blockDim.x + threadIdx.x;
    if (e < E) {
        int d = load_dst(ei32, E, e);
        if ((unsigned)d < (unsigned)N) atomicAdd(&g_cnt[d], 1);
    }
}

// ---------------------------------------------------------------------------
__global__ void __launch_bounds__(256) ra_scan1_kernel(int N) {
    __shared__ int wsum[8];
    int base = blockIdx.x * SCAN_CHUNK + threadIdx.x * 4;
    int s = 0;
#pragma unroll
    for (int j = 0; j < 4; ++j) {
        int i = base + j;
        if (i < N) s += g_cnt[i];
    }
#pragma unroll
    for (int o = 16; o > 0; o >>= 1) s += __shfl_xor_sync(0xffffffffu, s, o);
    if ((threadIdx.x & 31) == 0) wsum[threadIdx.x >> 5] = s;
    __syncthreads();
    if (threadIdx.x == 0) {
        int t = 0;
#pragma unroll
        for (int w = 0; w < 8; ++w) t += wsum[w];
        g_bsum[blockIdx.x] = t;
    }
}

__global__ void __launch_bounds__(256) ra_scan3_kernel(int nb, int N) {
    __shared__ int sb[128];
    __shared__ int wtot[4];
    __shared__ int wpre[8];
    int tid = threadIdx.x;
    int lane = tid & 31, w = tid >> 5;

    {
        int v = (tid < nb) ? g_bsum[tid] : 0;
        int incl = v;
#pragma unroll
        for (int o = 1; o < 32; o <<= 1) {
            int u = __shfl_up_sync(0xffffffffu, incl, o);
            if (lane >= o) incl += u;
        }
        if (lane == 31 && w < 4) wtot[w] = incl;
        __syncthreads();
        if (tid < 128) {
            int wbase = 0;
#pragma unroll
            for (int i = 0; i < 4; ++i) if (i < w) wbase += wtot[i];
            sb[tid] = wbase + incl - v;
        }
        __syncthreads();
        if (blockIdx.x == 0 && tid == 0) g_off[N] = sb[nb - 1] + g_bsum[nb - 1];
    }

    int bbase = sb[blockIdx.x];
    int base = blockIdx.x * SCAN_CHUNK + tid * 4;
    int c[4];
    int s = 0;
#pragma unroll
    for (int j = 0; j < 4; ++j) {
        int i = base + j;
        c[j] = (i < N) ? g_cnt[i] : 0;
        s += c[j];
    }
    int incl = s;
#pragma unroll
    for (int o = 1; o < 32; o <<= 1) {
        int u = __shfl_up_sync(0xffffffffu, incl, o);
        if (lane >= o) incl += u;
    }
    if (lane == 31) wpre[w] = incl;
    __syncthreads();
    int run = bbase + incl - s;
#pragma unroll
    for (int i = 0; i < 8; ++i) if (i < w) run += wpre[i];
#pragma unroll
    for (int j = 0; j < 4; ++j) {
        int i = base + j;
        if (i < N) { g_off[i] = run; g_cursor[i] = run; }
        run += c[j];
    }
}

// ---------------------------------------------------------------------------
__global__ void ra_scatter_kernel(const int* __restrict__ ei32, int E, int N) {
    int e = blockIdx.x * blockDim.x + threadIdx.x;
    if (e < E) {
        int s = load_src(ei32, E, e);
        int d = load_dst(ei32, E, e);
        if ((unsigned)d < (unsigned)N && (unsigned)s < (unsigned)N) {
            int p = atomicAdd(&g_cursor[d], 1);
            g_srcsort[p] = s;
        }
    }
}

// ---------------------------------------------------------------------------
// Packed f32x2 helpers (operate directly on the 64-bit register pairs that
// LDG.128 already produces — no packing cost).
// ---------------------------------------------------------------------------
#define MUL2D(d, a, b)    asm("mul.rn.f32x2 %0, %1, %2;" : "=l"(d) : "l"(a), "l"(b))
#define FMA2A(acc, a, b)  asm("fma.rn.f32x2 %0, %1, %2, %0;" : "+l"(acc) : "l"(a), "l"(b))
#define ADD2A(acc, a)     asm("add.rn.f32x2 %0, %1, %0;" : "+l"(acc) : "l"(a))
#define PACKDUP(d, a)     asm("mov.b64 %0, {%1, %1};" : "=l"(d) : "f"(a))
#define PACK2(d, a)       PACKDUP(d, a)
#define UNPK(lo, hi, v)   asm("mov.b64 {%0, %1}, %2;" : "=f"(lo), "=f"(hi) : "l"(v))
#define UNPACK2(lo, hi, v) UNPK(lo, hi, v)
#define FMA2(acc, a, b)   FMA2A(acc, a, b)

// one edge-pair accumulation step on register pair xv (both halves valid)
#define AGG_STEP(xv)                                                        \
    do {                                                                    \
        unsigned long long tdp;                                             \
        MUL2D(tdp, (xv).x, xdv.x);                                          \
        FMA2A(tdp, (xv).y, xdv.y);                                          \
        float plo, phi; UNPK(plo, phi, tdp);                                \
        float p = plo + phi;                                                \
        p += __shfl_xor_sync(0xffffffffu, p, 8);                            \
        p += __shfl_xor_sync(0xffffffffu, p, 4);                            \
        p += __shfl_xor_sync(0xffffffffu, p, 2);                            \
        p += __shfl_xor_sync(0xffffffffu, p, 1);                            \
        float wgt = __expf(p * 0.125f);                                     \
        denom += wgt;                                                       \
        unsigned long long w2; PACKDUP(w2, wgt);                            \
        FMA2A(mg0, w2, (xv).x); FMA2A(mg1, w2, (xv).y);                     \
        ADD2A(s0, (xv).x);      ADD2A(s1, (xv).y);                          \
        FMA2A(q0, (xv).x, (xv).x); FMA2A(q1, (xv).y, (xv).y);               \
    } while (0)

// ---------------------------------------------------------------------------
// Pass 4: one warp per dst node. Half-warp h owns edges b+2t+h; lane owns
// 4 dims (one LDG.128 = two f32x2 pairs). Unroll-2 over edge pairs with both
// loads issued up front; all prefetch indices clamped to e-1 so the loop has
// NO validity logic; odd tail reads the clamped row already in registers.
// Direct exp (shift-invariant softmax, logits ~N(0,1)).
// ---------------------------------------------------------------------------
__global__ void __launch_bounds__(256)
ra_agg_kernel(const float* __restrict__ x, int N) {
    int gtid = blockIdx.x * blockDim.x + threadIdx.x;
    int n = gtid >> 5;
    if (n >= N) return;
    int lane = threadIdx.x & 31;
    int half = lane >> 4;
    int hl   = lane & 15;

    int b = g_off[n];
    int e = g_off[n + 1];
    int cnt = e - b;

    float* row = g_msgvar + (size_t)n * 128;
    if (cnt == 0) {
        if (half == 0) {
            *reinterpret_cast<float4*>(row + 4 * hl)      = make_float4(0.f, 0.f, 0.f, 0.f);
            *reinterpret_cast<float4*>(row + 64 + 4 * hl) = make_float4(0.f, 0.f, 0.f, 0.f);
        }
        return;
    }

    ulonglong2 xdv = *reinterpret_cast<const ulonglong2*>(x + (size_t)n * 64 + 4 * hl);

    unsigned long long mg0 = 0, mg1 = 0, s0 = 0, s1 = 0, q0 = 0, q1 = 0;
    float denom = 0.f;

    int pairs = cnt >> 1;

    // invariant: xs holds the (clamped) row for pair t
    int t = 0;
    ulonglong2 xs;
    {
        int i0 = min(b + half, e - 1);
        int sidx = g_srcsort[i0];
        xs = *reinterpret_cast<const ulonglong2*>(x + (size_t)sidx * 64 + 4 * hl);
    }

    // unroll-2 main loop: both next loads issued before computing
    while (t + 2 <= pairs) {
        int ia = min(b + 2 * (t + 1) + half, e - 1);
        int ib = min(b + 2 * (t + 2) + half, e - 1);
        int sa = g_srcsort[ia];
        int sb = g_srcsort[ib];
        ulonglong2 xa = *reinterpret_cast<const ulonglong2*>(x + (size_t)sa * 64 + 4 * hl);
        ulonglong2 xb = *reinterpret_cast<const ulonglong2*>(x + (size_t)sb * 64 + 4 * hl);

        AGG_STEP(xs);
        AGG_STEP(xa);

        xs = xb;
        t += 2;
    }

    // at most one remaining full pair
    if (t < pairs) {
        int in = min(b + 2 * (t + 1) + half, e - 1);
        int sn = g_srcsort[in];
        ulonglong2 xn = *reinterpret_cast<const ulonglong2*>(x + (size_t)sn * 64 + 4 * hl);
        AGG_STEP(xs);
        xs = xn;
    }

    // odd tail: xs now holds x[srcsort[e-1]] in BOTH halves (clamped load)
    if (cnt & 1) {
        unsigned long long tdp;
        MUL2D(tdp, xs.x, xdv.x);
        FMA2A(tdp, xs.y, xdv.y);
        float plo, phi; UNPK(plo, phi, tdp);
        float p = plo + phi;
        p += __shfl_xor_sync(0xffffffffu, p, 8);
        p += __shfl_xor_sync(0xffffffffu, p, 4);
        p += __shfl_xor_sync(0xffffffffu, p, 2);
        p += __shfl_xor_sync(0xffffffffu, p, 1);
        float wgt = __expf(p * 0.125f);
        if (half == 0) {
            denom += wgt;
            unsigned long long w2; PACKDUP(w2, wgt);
            FMA2A(mg0, w2, xs.x); FMA2A(mg1, w2, xs.y);
            ADD2A(s0, xs.x);      ADD2A(s1, xs.y);
            FMA2A(q0, xs.x, xs.x); FMA2A(q1, xs.y, xs.y);
        }
    }

    float mgf[4], sf[4], qf[4];
    UNPK(mgf[0], mgf[1], mg0); UNPK(mgf[2], mgf[3], mg1);
    UNPK(sf[0],  sf[1],  s0);  UNPK(sf[2],  sf[3],  s1);
    UNPK(qf[0],  qf[1],  q0);  UNPK(qf[2],  qf[3],  q1);

    denom += __shfl_xor_sync(0xffffffffu, denom, 16);
#pragma unroll
    for (int j = 0; j < 4; ++j) {
        mgf[j] += __shfl_xor_sync(0xffffffffu, mgf[j], 16);
        sf[j]  += __shfl_xor_sync(0xffffffffu, sf[j], 16);
        qf[j]  += __shfl_xor_sync(0xffffffffu, qf[j], 16);
    }

    if (half == 0) {
        float invD = 1.0f / denom;
        float invc = 1.0f / (float)cnt;
        float4 var;
        float m0 = sf[0] * invc, m1 = sf[1] * invc, m2 = sf[2] * invc, m3 = sf[3] * invc;
        var.x = fmaxf(fmaf(-m0, m0, qf[0] * invc), 0.f);
        var.y = fmaxf(fmaf(-m1, m1, qf[1] * invc), 0.f);
        var.z = fmaxf(fmaf(-m2, m2, qf[2] * invc), 0.f);
        var.w = fmaxf(fmaf(-m3, m3, qf[3] * invc), 0.f);

        *reinterpret_cast<float4*>(row + 4 * hl) =
            make_float4(mgf[0] * invD, mgf[1] * invD, mgf[2] * invD, mgf[3] * invD);
        *reinterpret_cast<float4*>(row + 64 + 4 * hl) = var;
    }
}

// ---------------------------------------------------------------------------
// Pass 5: fused GEMM  out = x@Ws^T + msg@Wn^T + var@Wv^T + (bs+bn+bv)
// (R10 configuration: pitch-64 A tile, f32x2 packed FMA.)
// ---------------------------------------------------------------------------
__global__ void __launch_bounds__(256)
ra_gemm_kernel(const float* __restrict__ x,
               const float* __restrict__ Ws, const float* __restrict__ bs,
               const float* __restrict__ Wn, const float* __restrict__ bn,
               const float* __restrict__ Wv, const float* __restrict__ bv,
               float* __restrict__ out, int N) {
    __shared__ __align__(16) float Ash[128 * 64];
    __shared__ __align__(16) float Bsh[64 * 64];

    int tid = threadIdx.x;
    int tx = tid & 7;
    int ty = tid >> 3;
    int n0 = blockIdx.x * 128;

    unsigned long long acc[4][4];
#pragma unroll
    for (int r = 0; r < 4; ++r)
#pragma unroll
        for (int p = 0; p < 4; ++p) acc[r][p] = 0ull;

    for (int kc = 0; kc < 3; ++kc) {
        {
            const float* ap; int pitch, cb;
            if (kc == 0) { ap = x;        pitch = 64;  cb = 0; }
            else         { ap = g_msgvar; pitch = 128; cb = (kc - 1) * 64; }
            for (int i = tid; i < 128 * 64; i += 256) {
                int node = i >> 6, k = i & 63;
                int nn = n0 + node;
                Ash[i] = (nn < N) ? ap[(size_t)nn * pitch + cb + k] : 0.0f;
            }
        }
        {
            const float* wp = (kc == 0) ? Ws : ((kc == 1) ? Wn : Wv);
            for (int i = tid; i < 64 * 64; i += 256) {
                int ii = i >> 6;
                int kk = i & 63;
                int c4 = (ii >> 2) ^ (kk & 15);
                Bsh[kk * 64 + (c4 << 2) + (ii & 3)] = wp[i];
            }
        }
        __syncthreads();

        const float* arow = &Ash[(ty * 4) * 64];
        for (int k0 = 0; k0 < 64; k0 += 16) {
#pragma unroll
            for (int u = 0; u < 16; ++u) {
                int k = k0 + u;
                float a0 = arow[0 * 64 + k];
                float a1 = arow[1 * 64 + k];
                float a2 = arow[2 * 64 + k];
                float a3 = arow[3 * 64 + k];
                unsigned long long A0, A1, A2, A3;
                PACK2(A0, a0); PACK2(A1, a1); PACK2(A2, a2); PACK2(A3, a3);

                int sw0 = (((tx * 2)     ^ u) << 2);
                int sw1 = (((tx * 2 + 1) ^ u) << 2);
                ulonglong2 B0 = *reinterpret_cast<const ulonglong2*>(&Bsh[k * 64 + sw0]);
                ulonglong2 B1 = *reinterpret_cast<const ulonglong2*>(&Bsh[k * 64 + sw1]);

                FMA2(acc[0][0], A0, B0.x); FMA2(acc[0][1], A0, B0.y);
                FMA2(acc[0][2], A0, B1.x); FMA2(acc[0][3], A0, B1.y);
                FMA2(acc[1][0], A1, B0.x); FMA2(acc[1][1], A1, B0.y);
                FMA2(acc[1][2], A1, B1.x); FMA2(acc[1][3], A1, B1.y);
                FMA2(acc[2][0], A2, B0.x); FMA2(acc[2][1], A2, B0.y);
                FMA2(acc[2][2], A2, B1.x); FMA2(acc[2][3], A2, B1.y);
                FMA2(acc[3][0], A3, B0.x); FMA2(acc[3][1], A3, B0.y);
                FMA2(acc[3][2], A3, B1.x); FMA2(acc[3][3], A3, B1.y);
            }
        }
        __syncthreads();
    }

    float bsum[8];
#pragma unroll
    for (int p = 0; p < 8; ++p) {
        int d = tx * 8 + p;
        bsum[p] = bs[d] + bn[d] + bv[d];
    }
#pragma unroll
    for (int r = 0; r < 4; ++r) {
        int n = n0 + ty * 4 + r;
        if (n < N) {
            float o[8];
#pragma unroll
            for (int p = 0; p < 4; ++p) {
                float lo, hi;
                UNPACK2(lo, hi, acc[r][p]);
                o[2 * p]     = lo + bsum[2 * p];
                o[2 * p + 1] = hi + bsum[2 * p + 1];
            }
            float4* dst = reinterpret_cast<float4*>(out + (size_t)n * 64 + tx * 8);
            dst[0] = make_float4(o[0], o[1], o[2], o[3]);
            dst[1] = make_float4(o[4], o[5], o[6], o[7]);
        }
    }
}

// ---------------------------------------------------------------------------
extern "C" void kernel_launch(void* const* d_in, const int* in_sizes, int n_in,
                              void* d_out, int out_size) {
    const float* x  = (const float*)d_in[0];
    const int*   ei = (const int*)d_in[1];
    const float* Ws = (const float*)d_in[2];
    const float* bs = (const float*)d_in[3];
    const float* Wn = (const float*)d_in[4];
    const float* bn = (const float*)d_in[5];
    const float* Wv = (const float*)d_in[6];
    const float* bv = (const float*)d_in[7];
    float* out = (float*)d_out;

    int N = in_sizes[0] / 64;
    int E = in_sizes[1] / 2;
    int nb = (N + SCAN_CHUNK - 1) / SCAN_CHUNK;

    ra_init_kernel<<<(N + 255) / 256, 256>>>(ei, N);
    ra_hist_kernel<<<(E + 255) / 256, 256>>>(ei, E, N);
    ra_scan1_kernel<<<nb, 256>>>(N);
    ra_scan3_kernel<<<nb, 256>>>(nb, N);
    ra_scatter_kernel<<<(E + 255) / 256, 256>>>(ei, E, N);
    ra_agg_kernel<<<(N * 32 + 255) / 256, 256>>>(x, N);
    ra_gemm_kernel<<<(N + 127) / 128, 256>>>(x, Ws, bs, Wn, bn, Wv, bv, out, N);
}

// round 17
// speedup vs baseline: 1.2400x; 1.1869x over previous
#include <cuda_runtime.h>
#include <cuda_bf16.h>
#include <math.h>

#define MAXN 100352
#define MAXE 1600000
#define SCAN_CHUNK 1024

__device__ int   g_is64;
__device__ int   g_cnt[MAXN];
__device__ int   g_cursor[MAXN];
__device__ int   g_off[MAXN + 1];
__device__ int   g_bsum[128];
__device__ int   g_srcsort[MAXE];
__device__ float g_msgvar[(size_t)MAXN * 128]; // [N][0:64)=msg, [64:128)=var

// ---------------------------------------------------------------------------
// Pass 0: zero counters; block 0 also detects edge_index dtype
// ---------------------------------------------------------------------------
__global__ void ra_init_kernel(const int* __restrict__ ei32, int N) {
    int i = blockIdx.x * blockDim.x + threadIdx.x;
    if (i < N) g_cnt[i] = 0;
    if (blockIdx.x == 0) {
        __shared__ int nz;
        if (threadIdx.x == 0) nz = 0;
        __syncthreads();
        int v = ei32[2 * threadIdx.x + 1];
        if (v != 0) nz = 1;                  // benign race
        __syncthreads();
        if (threadIdx.x == 0) g_is64 = nz ? 0 : 1;
    }
}

__device__ __forceinline__ int load_src(const int* ei32, int E, int e) {
    return g_is64 ? ei32[2 * e] : ei32[e];
}
__device__ __forceinline__ int load_dst(const int* ei32, int E, int e) {
    return g_is64 ? ei32[2 * (E + e)] : ei32[E + e];
}

// ---------------------------------------------------------------------------
__global__ void ra_hist_kernel(const int* __restrict__ ei32, int E, int N) {
    int e = blockIdx.x * blockDim.x + threadIdx.x;
    if (e < E) {
        int d = load_dst(ei32, E, e);
        if ((unsigned)d < (unsigned)N) atomicAdd(&g_cnt[d], 1);
    }
}

// ---------------------------------------------------------------------------
__global__ void __launch_bounds__(256) ra_scan1_kernel(int N) {
    __shared__ int wsum[8];
    int base = blockIdx.x * SCAN_CHUNK + threadIdx.x * 4;
    int s = 0;
#pragma unroll
    for (int j = 0; j < 4; ++j) {
        int i = base + j;
        if (i < N) s += g_cnt[i];
    }
#pragma unroll
    for (int o = 16; o > 0; o >>= 1) s += __shfl_xor_sync(0xffffffffu, s, o);
    if ((threadIdx.x & 31) == 0) wsum[threadIdx.x >> 5] = s;
    __syncthreads();
    if (threadIdx.x == 0) {
        int t = 0;
#pragma unroll
        for (int w = 0; w < 8; ++w) t += wsum[w];
        g_bsum[blockIdx.x] = t;
    }
}

__global__ void __launch_bounds__(256) ra_scan3_kernel(int nb, int N) {
    __shared__ int sb[128];
    __shared__ int wtot[4];
    __shared__ int wpre[8];
    int tid = threadIdx.x;
    int lane = tid & 31, w = tid >> 5;

    {
        int v = (tid < nb) ? g_bsum[tid] : 0;
        int incl = v;
#pragma unroll
        for (int o = 1; o < 32; o <<= 1) {
            int u = __shfl_up_sync(0xffffffffu, incl, o);
            if (lane >= o) incl += u;
        }
        if (lane == 31 && w < 4) wtot[w] = incl;
        __syncthreads();
        if (tid < 128) {
            int wbase = 0;
#pragma unroll
            for (int i = 0; i < 4; ++i) if (i < w) wbase += wtot[i];
            sb[tid] = wbase + incl - v;
        }
        __syncthreads();
        if (blockIdx.x == 0 && tid == 0) g_off[N] = sb[nb - 1] + g_bsum[nb - 1];
    }

    int bbase = sb[blockIdx.x];
    int base = blockIdx.x * SCAN_CHUNK + tid * 4;
    int c[4];
    int s = 0;
#pragma unroll
    for (int j = 0; j < 4; ++j) {
        int i = base + j;
        c[j] = (i < N) ? g_cnt[i] : 0;
        s += c[j];
    }
    int incl = s;
#pragma unroll
    for (int o = 1; o < 32; o <<= 1) {
        int u = __shfl_up_sync(0xffffffffu, incl, o);
        if (lane >= o) incl += u;
    }
    if (lane == 31) wpre[w] = incl;
    __syncthreads();
    int run = bbase + incl - s;
#pragma unroll
    for (int i = 0; i < 8; ++i) if (i < w) run += wpre[i];
#pragma unroll
    for (int j = 0; j < 4; ++j) {
        int i = base + j;
        if (i < N) { g_off[i] = run; g_cursor[i] = run; }
        run += c[j];
    }
}

// ---------------------------------------------------------------------------
__global__ void ra_scatter_kernel(const int* __restrict__ ei32, int E, int N) {
    int e = blockIdx.x * blockDim.x + threadIdx.x;
    if (e < E) {
        int s = load_src(ei32, E, e);
        int d = load_dst(ei32, E, e);
        if ((unsigned)d < (unsigned)N && (unsigned)s < (unsigned)N) {
            int p = atomicAdd(&g_cursor[d], 1);
            g_srcsort[p] = s;
        }
    }
}

// ---------------------------------------------------------------------------
// Packed f32x2 helpers
// ---------------------------------------------------------------------------
#define MUL2D(d, a, b)    asm("mul.rn.f32x2 %0, %1, %2;" : "=l"(d) : "l"(a), "l"(b))
#define FMA2A(acc, a, b)  asm("fma.rn.f32x2 %0, %1, %2, %0;" : "+l"(acc) : "l"(a), "l"(b))
#define ADD2A(acc, a)     asm("add.rn.f32x2 %0, %1, %0;" : "+l"(acc) : "l"(a))
#define PACKDUP(d, a)     asm("mov.b64 %0, {%1, %1};" : "=l"(d) : "f"(a))
#define PACK2(d, a)       PACKDUP(d, a)
#define UNPK(lo, hi, v)   asm("mov.b64 {%0, %1}, %2;" : "=f"(lo), "=f"(hi) : "l"(v))
#define UNPACK2(lo, hi, v) UNPK(lo, hi, v)
#define FMA2(acc, a, b)   FMA2A(acc, a, b)

// ---------------------------------------------------------------------------
// Pass 4: one warp per dst node. Half-warp h owns edges b+2t+h; lane owns
// 4 dims (one LDG.128 = two f32x2 register pairs). Main loop has NO validity
// logic (full pairs only; prefetch clamped to e-1); odd tail handled once.
// (R14 body verbatim — best measured.)
// ---------------------------------------------------------------------------
__global__ void __launch_bounds__(256)
ra_agg_kernel(const float* __restrict__ x, int N) {
    int gtid = blockIdx.x * blockDim.x + threadIdx.x;
    int n = gtid >> 5;
    if (n >= N) return;
    int lane = threadIdx.x & 31;
    int half = lane >> 4;
    int hl   = lane & 15;

    int b = g_off[n];
    int e = g_off[n + 1];
    int cnt = e - b;

    float* row = g_msgvar + (size_t)n * 128;
    if (cnt == 0) {
        if (half == 0) {
            *reinterpret_cast<float4*>(row + 4 * hl)      = make_float4(0.f, 0.f, 0.f, 0.f);
            *reinterpret_cast<float4*>(row + 64 + 4 * hl) = make_float4(0.f, 0.f, 0.f, 0.f);
        }
        return;
    }

    ulonglong2 xdv = *reinterpret_cast<const ulonglong2*>(x + (size_t)n * 64 + 4 * hl);

    unsigned long long mg0 = 0, mg1 = 0, s0 = 0, s1 = 0, q0 = 0, q1 = 0;
    float denom = 0.f;

    int full = cnt >> 1;
    ulonglong2 xs;
    if (full > 0) {
        int sidx = g_srcsort[b + half];
        xs = *reinterpret_cast<const ulonglong2*>(x + (size_t)sidx * 64 + 4 * hl);
        for (int t = 0; t < full; ++t) {
            int i_nxt = min(b + 2 * (t + 1) + half, e - 1);
            int snxt = g_srcsort[i_nxt];
            ulonglong2 xn = *reinterpret_cast<const ulonglong2*>(x + (size_t)snxt * 64 + 4 * hl);

            unsigned long long tdp;
            MUL2D(tdp, xs.x, xdv.x);
            FMA2A(tdp, xs.y, xdv.y);
            float plo, phi; UNPK(plo, phi, tdp);
            float p = plo + phi;
            p += __shfl_xor_sync(0xffffffffu, p, 8);
            p += __shfl_xor_sync(0xffffffffu, p, 4);
            p += __shfl_xor_sync(0xffffffffu, p, 2);
            p += __shfl_xor_sync(0xffffffffu, p, 1);

            float wgt = __expf(p * 0.125f);
            denom += wgt;
            unsigned long long w2; PACKDUP(w2, wgt);
            FMA2A(mg0, w2, xs.x); FMA2A(mg1, w2, xs.y);
            ADD2A(s0, xs.x);      ADD2A(s1, xs.y);
            FMA2A(q0, xs.x, xs.x); FMA2A(q1, xs.y, xs.y);

            xs = xn;
        }
    } else {
        int sidx = g_srcsort[e - 1];
        xs = *reinterpret_cast<const ulonglong2*>(x + (size_t)sidx * 64 + 4 * hl);
    }

    if (cnt & 1) {
        unsigned long long tdp;
        MUL2D(tdp, xs.x, xdv.x);
        FMA2A(tdp, xs.y, xdv.y);
        float plo, phi; UNPK(plo, phi, tdp);
        float p = plo + phi;
        p += __shfl_xor_sync(0xffffffffu, p, 8);
        p += __shfl_xor_sync(0xffffffffu, p, 4);
        p += __shfl_xor_sync(0xffffffffu, p, 2);
        p += __shfl_xor_sync(0xffffffffu, p, 1);
        float wgt = __expf(p * 0.125f);
        if (half == 0) {
            denom += wgt;
            unsigned long long w2; PACKDUP(w2, wgt);
            FMA2A(mg0, w2, xs.x); FMA2A(mg1, w2, xs.y);
            ADD2A(s0, xs.x);      ADD2A(s1, xs.y);
            FMA2A(q0, xs.x, xs.x); FMA2A(q1, xs.y, xs.y);
        }
    }

    float mgf[4], sf[4], qf[4];
    UNPK(mgf[0], mgf[1], mg0); UNPK(mgf[2], mgf[3], mg1);
    UNPK(sf[0],  sf[1],  s0);  UNPK(sf[2],  sf[3],  s1);
    UNPK(qf[0],  qf[1],  q0);  UNPK(qf[2],  qf[3],  q1);

    denom += __shfl_xor_sync(0xffffffffu, denom, 16);
#pragma unroll
    for (int j = 0; j < 4; ++j) {
        mgf[j] += __shfl_xor_sync(0xffffffffu, mgf[j], 16);
        sf[j]  += __shfl_xor_sync(0xffffffffu, sf[j], 16);
        qf[j]  += __shfl_xor_sync(0xffffffffu, qf[j], 16);
    }

    if (half == 0) {
        float invD = 1.0f / denom;
        float invc = 1.0f / (float)cnt;
        float4 var;
        float m0 = sf[0] * invc, m1 = sf[1] * invc, m2 = sf[2] * invc, m3 = sf[3] * invc;
        var.x = fmaxf(fmaf(-m0, m0, qf[0] * invc), 0.f);
        var.y = fmaxf(fmaf(-m1, m1, qf[1] * invc), 0.f);
        var.z = fmaxf(fmaf(-m2, m2, qf[2] * invc), 0.f);
        var.w = fmaxf(fmaf(-m3, m3, qf[3] * invc), 0.f);

        *reinterpret_cast<float4*>(row + 4 * hl) =
            make_float4(mgf[0] * invD, mgf[1] * invD, mgf[2] * invD, mgf[3] * invD);
        *reinterpret_cast<float4*>(row + 64 + 4 * hl) = var;
    }
}

// ---------------------------------------------------------------------------
// Pass 5: fused GEMM  out = x@Ws^T + msg@Wn^T + var@Wv^T + (bs+bn+bv)
// Thread tile widened to 8 nodes x 8 dims (128 threads/block, same 128x64
// block tile): FMA2:LDS ratio 32:10 vs 16:6, double per-thread ILP.
// ---------------------------------------------------------------------------
__global__ void __launch_bounds__(128)
ra_gemm_kernel(const float* __restrict__ x,
               const float* __restrict__ Ws, const float* __restrict__ bs,
               const float* __restrict__ Wn, const float* __restrict__ bn,
               const float* __restrict__ Wv, const float* __restrict__ bv,
               float* __restrict__ out, int N) {
    __shared__ __align__(16) float Ash[128 * 64];
    __shared__ __align__(16) float Bsh[64 * 64];

    int tid = threadIdx.x;
    int tx = tid & 7;          // dim group: dims tx*8 .. tx*8+7
    int ty = tid >> 3;         // node group: nodes ty*8 .. ty*8+7
    int n0 = blockIdx.x * 128;

    unsigned long long acc[8][4];
#pragma unroll
    for (int r = 0; r < 8; ++r)
#pragma unroll
        for (int p = 0; p < 4; ++p) acc[r][p] = 0ull;

    for (int kc = 0; kc < 3; ++kc) {
        {
            const float* ap; int pitch, cb;
            if (kc == 0) { ap = x;        pitch = 64;  cb = 0; }
            else         { ap = g_msgvar; pitch = 128; cb = (kc - 1) * 64; }
            for (int i = tid; i < 128 * 16; i += 128) {
                int node = i >> 4, kq = i & 15;     // 4 floats per slot
                int nn = n0 + node;
                float4 v = (nn < N)
                    ? *reinterpret_cast<const float4*>(ap + (size_t)nn * pitch + cb + kq * 4)
                    : make_float4(0.f, 0.f, 0.f, 0.f);
                *reinterpret_cast<float4*>(&Ash[node * 64 + kq * 4]) = v;
            }
        }
        {
            const float* wp = (kc == 0) ? Ws : ((kc == 1) ? Wn : Wv);
            for (int i = tid; i < 64 * 64; i += 128) {
                int ii = i >> 6;
                int kk = i & 63;
                int c4 = (ii >> 2) ^ (kk & 15);
                Bsh[kk * 64 + (c4 << 2) + (ii & 3)] = wp[i];
            }
        }
        __syncthreads();

        const float* arow = &Ash[(ty * 8) * 64];
        for (int k0 = 0; k0 < 64; k0 += 16) {
#pragma unroll
            for (int u = 0; u < 16; ++u) {
                int k = k0 + u;
                unsigned long long A[8];
#pragma unroll
                for (int r = 0; r < 8; ++r) {
                    float a = arow[r * 64 + k];
                    PACKDUP(A[r], a);
                }
                int sw0 = (((tx * 2)     ^ u) << 2);
                int sw1 = (((tx * 2 + 1) ^ u) << 2);
                ulonglong2 B0 = *reinterpret_cast<const ulonglong2*>(&Bsh[k * 64 + sw0]);
                ulonglong2 B1 = *reinterpret_cast<const ulonglong2*>(&Bsh[k * 64 + sw1]);
#pragma unroll
                for (int r = 0; r < 8; ++r) {
                    FMA2A(acc[r][0], A[r], B0.x); FMA2A(acc[r][1], A[r], B0.y);
                    FMA2A(acc[r][2], A[r], B1.x); FMA2A(acc[r][3], A[r], B1.y);
                }
            }
        }
        __syncthreads();
    }

    float bsum[8];
#pragma unroll
    for (int p = 0; p < 8; ++p) {
        int d = tx * 8 + p;
        bsum[p] = bs[d] + bn[d] + bv[d];
    }
#pragma unroll
    for (int r = 0; r < 8; ++r) {
        int n = n0 + ty * 8 + r;
        if (n < N) {
            float o[8];
#pragma unroll
            for (int p = 0; p < 4; ++p) {
                float lo, hi;
                UNPK(lo, hi, acc[r][p]);
                o[2 * p]     = lo + bsum[2 * p];
                o[2 * p + 1] = hi + bsum[2 * p + 1];
            }
            float4* dst = reinterpret_cast<float4*>(out + (size_t)n * 64 + tx * 8);
            dst[0] = make_float4(o[0], o[1], o[2], o[3]);
            dst[1] = make_float4(o[4], o[5], o[6], o[7]);
        }
    }
}

// ---------------------------------------------------------------------------
extern "C" void kernel_launch(void* const* d_in, const int* in_sizes, int n_in,
                              void* d_out, int out_size) {
    const float* x  = (const float*)d_in[0];
    const int*   ei = (const int*)d_in[1];
    const float* Ws = (const float*)d_in[2];
    const float* bs = (const float*)d_in[3];
    const float* Wn = (const float*)d_in[4];
    const float* bn = (const float*)d_in[5];
    const float* Wv = (const float*)d_in[6];
    const float* bv = (const float*)d_in[7];
    float* out = (float*)d_out;

    int N = in_sizes[0] / 64;
    int E = in_sizes[1] / 2;
    int nb = (N + SCAN_CHUNK - 1) / SCAN_CHUNK;

    ra_init_kernel<<<(N + 255) / 256, 256>>>(ei, N);
    ra_hist_kernel<<<(E + 255) / 256, 256>>>(ei, E, N);
    ra_scan1_kernel<<<nb, 256>>>(N);
    ra_scan3_kernel<<<nb, 256>>>(nb, N);
    ra_scatter_kernel<<<(E + 255) / 256, 256>>>(ei, E, N);
    ra_agg_kernel<<<(N * 32 + 255) / 256, 256>>>(x, N);
    ra_gemm_kernel<<<(N + 127) / 128, 128>>>(x, Ws, bs, Wn, bn, Wv, bv, out, N);
}